// round 10
// baseline (speedup 1.0000x reference)
#include <cuda_runtime.h>
#include <cuda_bf16.h>
#include <cstdint>

#define B_  16384
#define L_  50
#define PS  68     // padded row stride (uint32 words) for smem planes

// Packed bf16 hi/lo planes: his [B][64 words], W [128][64 words]
__device__ uint32_t g_hhi[B_ * 64];
__device__ uint32_t g_hlo[B_ * 64];
__device__ uint32_t g_whi[128 * 64];
__device__ uint32_t g_wlo[128 * 64];

__device__ __forceinline__ void split_bf16(float x, uint32_t& h, uint32_t& l) {
    uint16_t hb = __bfloat16_as_ushort(__float2bfloat16_rn(x));
    float hf = __uint_as_float(((uint32_t)hb) << 16);
    uint16_t lb = __bfloat16_as_ushort(__float2bfloat16_rn(x - hf));
    h = hb; l = lb;
}
__device__ __forceinline__ uint32_t pack2(uint32_t lo16, uint32_t hi16) {
    return (lo16 & 0xFFFFu) | (hi16 << 16);
}
__device__ __forceinline__ void mma_bf16(float c[4], const uint32_t a[4],
                                         uint32_t b0, uint32_t b1) {
    asm volatile(
        "mma.sync.aligned.m16n8k16.row.col.f32.bf16.bf16.f32 "
        "{%0,%1,%2,%3}, {%4,%5,%6,%7}, {%8,%9}, {%0,%1,%2,%3};"
        : "+f"(c[0]), "+f"(c[1]), "+f"(c[2]), "+f"(c[3])
        : "r"(a[0]), "r"(a[1]), "r"(a[2]), "r"(a[3]), "r"(b0), "r"(b1));
}

// ---------------------------------------------------------------------------
// Kernel 1: masked gather-sum -> packed bf16 hi/lo planes.
// CTA 0 additionally pre-splits W into g_whi/g_wlo (hidden under DRAM wait).
// ---------------------------------------------------------------------------
__global__ __launch_bounds__(256) void gather_kernel(
    const int*    __restrict__ entities,
    const int*    __restrict__ history,
    const int*    __restrict__ hist_len,
    const float4* __restrict__ embv,
    const float4* __restrict__ Wv)
{
    const int warp = threadIdx.x >> 5;
    const int lane = threadIdx.x & 31;
    const int b    = (blockIdx.x << 3) + warp;

    // CTA 0: split W once (4096 float4 across 256 threads)
    if (blockIdx.x == 0) {
        for (int t = threadIdx.x; t < 128 * 32; t += 256) {
            const int j  = t >> 5;
            const int kv = t & 31;
            float4 w = Wv[j * 32 + kv];
            uint32_t h0,l0,h1,l1,h2,l2,h3,l3;
            split_bf16(w.x, h0, l0); split_bf16(w.y, h1, l1);
            split_bf16(w.z, h2, l2); split_bf16(w.w, h3, l3);
            ((uint2*)g_whi)[j * 32 + kv] = make_uint2(pack2(h0,h1), pack2(h2,h3));
            ((uint2*)g_wlo)[j * 32 + kv] = make_uint2(pack2(l0,l1), pack2(l2,l3));
        }
    }

    __shared__ int sh_idx[8][52];

    const int n = hist_len[b];
    for (int l = lane; l < n; l += 32)
        sh_idx[warp][l] = history[b * L_ + l];
    __syncwarp();

    float4 a0 = make_float4(0.f, 0.f, 0.f, 0.f);
    float4 a1 = a0, a2 = a0, a3 = a0;

    int l = 0;
    for (; l + 4 <= n; l += 4) {
        const long i0 = sh_idx[warp][l + 0];
        const long i1 = sh_idx[warp][l + 1];
        const long i2 = sh_idx[warp][l + 2];
        const long i3 = sh_idx[warp][l + 3];
        float4 v0 = __ldg(&embv[i0 * 32 + lane]);
        float4 v1 = __ldg(&embv[i1 * 32 + lane]);
        float4 v2 = __ldg(&embv[i2 * 32 + lane]);
        float4 v3 = __ldg(&embv[i3 * 32 + lane]);
        a0.x += v0.x; a0.y += v0.y; a0.z += v0.z; a0.w += v0.w;
        a1.x += v1.x; a1.y += v1.y; a1.z += v1.z; a1.w += v1.w;
        a2.x += v2.x; a2.y += v2.y; a2.z += v2.z; a2.w += v2.w;
        a3.x += v3.x; a3.y += v3.y; a3.z += v3.z; a3.w += v3.w;
    }
    for (; l < n; l++) {
        const long i0 = sh_idx[warp][l];
        float4 v0 = __ldg(&embv[i0 * 32 + lane]);
        a0.x += v0.x; a0.y += v0.y; a0.z += v0.z; a0.w += v0.w;
    }

    float4 acc;
    acc.x = (a0.x + a1.x) + (a2.x + a3.x);
    acc.y = (a0.y + a1.y) + (a2.y + a3.y);
    acc.z = (a0.z + a1.z) + (a2.z + a3.z);
    acc.w = (a0.w + a1.w) + (a2.w + a3.w);

    if (n == 0)
        acc = __ldg(&embv[(long)entities[b] * 32 + lane]);

    // split + pack: lane covers k = 4*lane..4*lane+3 -> words 2*lane, 2*lane+1
    uint32_t h0,l0,h1,l1,h2,l2,h3,l3;
    split_bf16(acc.x, h0, l0); split_bf16(acc.y, h1, l1);
    split_bf16(acc.z, h2, l2); split_bf16(acc.w, h3, l3);
    ((uint2*)g_hhi)[(long)b * 32 + lane] = make_uint2(pack2(h0,h1), pack2(h2,h3));
    ((uint2*)g_hlo)[(long)b * 32 + lane] = make_uint2(pack2(l0,l1), pack2(l2,l3));
}

// ---------------------------------------------------------------------------
// Kernel 2: out = his @ W^T + bias, 3-pass split-bf16 mma.m16n8k16.
// CTA = 64 rows x 64 cols (half of W), grid 512, 68KB smem -> 3 CTAs/SM.
// Warp = 16 rows x 32 cols (4 n-tiles).
// ---------------------------------------------------------------------------
__global__ __launch_bounds__(256, 3) void linear_kernel(
    const float* __restrict__ bias,
    float*       __restrict__ out)
{
    extern __shared__ uint32_t sm[];
    uint32_t* aHi = sm;                 // [64][PS]
    uint32_t* aLo = aHi + 64 * PS;
    uint32_t* bHi = aLo + 64 * PS;      // [64][PS] (this CTA's 64 W rows)
    uint32_t* bLo = bHi + 64 * PS;

    const int tid  = threadIdx.x;
    const int lane = tid & 31;
    const int warp = tid >> 5;
    const int gq   = lane >> 2;
    const int tq   = lane & 3;
    const int wm   = warp >> 1;          // 0..3 : 16-row group
    const int wn   = warp & 1;           // 0..1 : 32-col group
    const int tile = blockIdx.x >> 1;
    const int half = blockIdx.x & 1;
    const int row0 = tile * 64;
    const int col0 = half * 64;

    // ---- Stage: pure uint4 copies, no ALU ----
    {
        const uint4* sAh = (const uint4*)g_hhi + (long)row0 * 16;
        const uint4* sAl = (const uint4*)g_hlo + (long)row0 * 16;
        const uint4* sBh = (const uint4*)g_whi + (long)col0 * 16;
        const uint4* sBl = (const uint4*)g_wlo + (long)col0 * 16;
        for (int t = tid; t < 64 * 16; t += 256) {
            const int r = t >> 4;
            const int q = t & 15;
            *(uint4*)&aHi[r * PS + q * 4] = sAh[t];
            *(uint4*)&aLo[r * PS + q * 4] = sAl[t];
            *(uint4*)&bHi[r * PS + q * 4] = sBh[t];
            *(uint4*)&bLo[r * PS + q * 4] = sBl[t];
        }
    }
    __syncthreads();

    // Accumulators initialized with bias.
    float c[4][4];
#pragma unroll
    for (int n = 0; n < 4; n++) {
        const int col = col0 + wn * 32 + n * 8 + 2 * tq;
        const float b0 = __ldg(&bias[col]);
        const float b1 = __ldg(&bias[col + 1]);
        c[n][0] = b0; c[n][1] = b1;
        c[n][2] = b0; c[n][3] = b1;
    }

    const int r = wm * 16 + gq;
#pragma unroll
    for (int kt = 0; kt < 8; kt++) {
        const int kp = kt * 8 + tq;
        uint32_t ahi[4], alo[4];
        ahi[0] = aHi[r * PS + kp];
        ahi[1] = aHi[(r + 8) * PS + kp];
        ahi[2] = aHi[r * PS + kp + 4];
        ahi[3] = aHi[(r + 8) * PS + kp + 4];
        alo[0] = aLo[r * PS + kp];
        alo[1] = aLo[(r + 8) * PS + kp];
        alo[2] = aLo[r * PS + kp + 4];
        alo[3] = aLo[(r + 8) * PS + kp + 4];

#pragma unroll
        for (int n = 0; n < 4; n++) {
            const int jl = wn * 32 + n * 8 + gq;    // local W row
            uint32_t bh0 = bHi[jl * PS + kp];
            uint32_t bh1 = bHi[jl * PS + kp + 4];
            uint32_t bl0 = bLo[jl * PS + kp];
            uint32_t bl1 = bLo[jl * PS + kp + 4];
            mma_bf16(c[n], ahi, bh0, bh1);   // Ah*Bh
            mma_bf16(c[n], ahi, bl0, bl1);   // Ah*Bl
            mma_bf16(c[n], alo, bh0, bh1);   // Al*Bh
        }
    }

    // Epilogue
#pragma unroll
    for (int n = 0; n < 4; n++) {
        const int rg  = row0 + wm * 16 + gq;
        const int col = col0 + wn * 32 + n * 8 + 2 * tq;
        *(float2*)&out[(long)rg * 128 + col]       = make_float2(c[n][0], c[n][1]);
        *(float2*)&out[(long)(rg + 8) * 128 + col] = make_float2(c[n][2], c[n][3]);
    }
}

// ---------------------------------------------------------------------------
extern "C" void kernel_launch(void* const* d_in, const int* in_sizes, int n_in,
                              void* d_out, int out_size)
{
    const int*   entities = (const int*)d_in[0];
    const int*   history  = (const int*)d_in[1];
    const int*   hist_len = (const int*)d_in[2];
    const float* emb      = (const float*)d_in[3];
    const float* W        = (const float*)d_in[4];
    const float* bias     = (const float*)d_in[5];
    float*       out      = (float*)d_out;

    gather_kernel<<<B_ / 8, 256>>>(entities, history, hist_len,
                                   (const float4*)emb, (const float4*)W);

    const size_t smem = (size_t)4 * 64 * PS * sizeof(uint32_t);   // 68 KB
    cudaFuncSetAttribute(linear_kernel,
                         cudaFuncAttributeMaxDynamicSharedMemorySize,
                         (int)smem);
    linear_kernel<<<(B_ / 64) * 2, 256, smem>>>(bias, out);
}

// round 11
// speedup vs baseline: 1.1169x; 1.1169x over previous
#include <cuda_runtime.h>
#include <cuda_bf16.h>
#include <cstdint>

#define B_  16384
#define L_  50
#define PS  68     // padded row stride (uint32 words) for smem planes

// his packed planes: per row 128 words = 32 quads [hiw0,hiw1,low0,low1]
__device__ uint32_t g_hpk[B_ * 128];
// W planes (split once)
__device__ uint32_t g_whi[128 * 64];
__device__ uint32_t g_wlo[128 * 64];

__device__ __forceinline__ void split_bf16(float x, uint32_t& h, uint32_t& l) {
    uint16_t hb = __bfloat16_as_ushort(__float2bfloat16_rn(x));
    float hf = __uint_as_float(((uint32_t)hb) << 16);
    uint16_t lb = __bfloat16_as_ushort(__float2bfloat16_rn(x - hf));
    h = hb; l = lb;
}
__device__ __forceinline__ uint32_t pack2(uint32_t lo16, uint32_t hi16) {
    return (lo16 & 0xFFFFu) | (hi16 << 16);
}
__device__ __forceinline__ void mma_bf16(float c[4], const uint32_t a[4],
                                         uint32_t b0, uint32_t b1) {
    asm volatile(
        "mma.sync.aligned.m16n8k16.row.col.f32.bf16.bf16.f32 "
        "{%0,%1,%2,%3}, {%4,%5,%6,%7}, {%8,%9}, {%0,%1,%2,%3};"
        : "+f"(c[0]), "+f"(c[1]), "+f"(c[2]), "+f"(c[3])
        : "r"(a[0]), "r"(a[1]), "r"(a[2]), "r"(a[3]), "r"(b0), "r"(b1));
}

// ---------------------------------------------------------------------------
// Kernel 1: masked gather-sum -> packed interleaved bf16 hi/lo (1 STG.128).
// CTA 0 pre-splits W (hidden under DRAM wait).
// ---------------------------------------------------------------------------
__global__ __launch_bounds__(256) void gather_kernel(
    const int*    __restrict__ entities,
    const int*    __restrict__ history,
    const int*    __restrict__ hist_len,
    const float4* __restrict__ embv,
    const float4* __restrict__ Wv)
{
    const int warp = threadIdx.x >> 5;
    const int lane = threadIdx.x & 31;
    const int b    = (blockIdx.x << 3) + warp;

    if (blockIdx.x == 0) {
        for (int t = threadIdx.x; t < 128 * 32; t += 256) {
            const int j  = t >> 5;
            const int kv = t & 31;
            float4 w = Wv[j * 32 + kv];
            uint32_t h0,l0,h1,l1,h2,l2,h3,l3;
            split_bf16(w.x, h0, l0); split_bf16(w.y, h1, l1);
            split_bf16(w.z, h2, l2); split_bf16(w.w, h3, l3);
            ((uint2*)g_whi)[j * 32 + kv] = make_uint2(pack2(h0,h1), pack2(h2,h3));
            ((uint2*)g_wlo)[j * 32 + kv] = make_uint2(pack2(l0,l1), pack2(l2,l3));
        }
    }

    __shared__ int sh_idx[8][52];

    const int n = hist_len[b];
    for (int l = lane; l < n; l += 32)
        sh_idx[warp][l] = history[b * L_ + l];
    __syncwarp();

    float4 a0 = make_float4(0.f, 0.f, 0.f, 0.f);
    float4 a1 = a0, a2 = a0, a3 = a0;

    int l = 0;
    for (; l + 4 <= n; l += 4) {
        const long i0 = sh_idx[warp][l + 0];
        const long i1 = sh_idx[warp][l + 1];
        const long i2 = sh_idx[warp][l + 2];
        const long i3 = sh_idx[warp][l + 3];
        float4 v0 = __ldg(&embv[i0 * 32 + lane]);
        float4 v1 = __ldg(&embv[i1 * 32 + lane]);
        float4 v2 = __ldg(&embv[i2 * 32 + lane]);
        float4 v3 = __ldg(&embv[i3 * 32 + lane]);
        a0.x += v0.x; a0.y += v0.y; a0.z += v0.z; a0.w += v0.w;
        a1.x += v1.x; a1.y += v1.y; a1.z += v1.z; a1.w += v1.w;
        a2.x += v2.x; a2.y += v2.y; a2.z += v2.z; a2.w += v2.w;
        a3.x += v3.x; a3.y += v3.y; a3.z += v3.z; a3.w += v3.w;
    }
    for (; l < n; l++) {
        const long i0 = sh_idx[warp][l];
        float4 v0 = __ldg(&embv[i0 * 32 + lane]);
        a0.x += v0.x; a0.y += v0.y; a0.z += v0.z; a0.w += v0.w;
    }

    float4 acc;
    acc.x = (a0.x + a1.x) + (a2.x + a3.x);
    acc.y = (a0.y + a1.y) + (a2.y + a3.y);
    acc.z = (a0.z + a1.z) + (a2.z + a3.z);
    acc.w = (a0.w + a1.w) + (a2.w + a3.w);

    if (n == 0)
        acc = __ldg(&embv[(long)entities[b] * 32 + lane]);

    uint32_t h0,l0,h1,l1,h2,l2,h3,l3;
    split_bf16(acc.x, h0, l0); split_bf16(acc.y, h1, l1);
    split_bf16(acc.z, h2, l2); split_bf16(acc.w, h3, l3);
    ((uint4*)g_hpk)[(long)b * 32 + lane] =
        make_uint4(pack2(h0,h1), pack2(h2,h3), pack2(l0,l1), pack2(l2,l3));
}

// ---------------------------------------------------------------------------
// Kernel 2: out = his @ W^T + bias, 3-pass split-bf16 mma.m16n8k16.
// CTA = 64 rows x 64 cols, grid 512, 68KB smem -> 3 CTAs/SM.
// Two accumulator chains (cA = AhBh + bias, cB = AhBl + AlBh).
// ---------------------------------------------------------------------------
__global__ __launch_bounds__(256, 3) void linear_kernel(
    const float* __restrict__ bias,
    float*       __restrict__ out)
{
    extern __shared__ uint32_t sm[];
    uint32_t* aHi = sm;                 // [64][PS]
    uint32_t* aLo = aHi + 64 * PS;
    uint32_t* bHi = aLo + 64 * PS;
    uint32_t* bLo = bHi + 64 * PS;

    const int tid  = threadIdx.x;
    const int lane = tid & 31;
    const int warp = tid >> 5;
    const int gq   = lane >> 2;
    const int tq   = lane & 3;
    const int wm   = warp >> 1;
    const int wn   = warp & 1;
    const int tile = blockIdx.x >> 1;
    const int half = blockIdx.x & 1;
    const int row0 = tile * 64;
    const int col0 = half * 64;

    // ---- Stage A (de-interleave packed quads) and B (direct copies) ----
    {
        const uint4* sA = (const uint4*)g_hpk + (long)row0 * 32;
        for (int t = tid; t < 64 * 32; t += 256) {
            const int r = t >> 5;
            const int q = t & 31;
            uint4 v = sA[t];
            *(uint2*)&aHi[r * PS + q * 2] = make_uint2(v.x, v.y);
            *(uint2*)&aLo[r * PS + q * 2] = make_uint2(v.z, v.w);
        }
        const uint4* sBh = (const uint4*)g_whi + (long)col0 * 16;
        const uint4* sBl = (const uint4*)g_wlo + (long)col0 * 16;
        for (int t = tid; t < 64 * 16; t += 256) {
            const int r = t >> 4;
            const int q = t & 15;
            *(uint4*)&bHi[r * PS + q * 4] = sBh[t];
            *(uint4*)&bLo[r * PS + q * 4] = sBl[t];
        }
    }
    __syncthreads();

    float cA[4][4], cB[4][4];
#pragma unroll
    for (int n = 0; n < 4; n++) {
        const int col = col0 + wn * 32 + n * 8 + 2 * tq;
        const float b0 = __ldg(&bias[col]);
        const float b1 = __ldg(&bias[col + 1]);
        cA[n][0] = b0;  cA[n][1] = b1;
        cA[n][2] = b0;  cA[n][3] = b1;
        cB[n][0] = 0.f; cB[n][1] = 0.f;
        cB[n][2] = 0.f; cB[n][3] = 0.f;
    }

    const int r = wm * 16 + gq;
#pragma unroll
    for (int kt = 0; kt < 8; kt++) {
        const int kp = kt * 8 + tq;
        uint32_t ahi[4], alo[4];
        ahi[0] = aHi[r * PS + kp];
        ahi[1] = aHi[(r + 8) * PS + kp];
        ahi[2] = aHi[r * PS + kp + 4];
        ahi[3] = aHi[(r + 8) * PS + kp + 4];
        alo[0] = aLo[r * PS + kp];
        alo[1] = aLo[(r + 8) * PS + kp];
        alo[2] = aLo[r * PS + kp + 4];
        alo[3] = aLo[(r + 8) * PS + kp + 4];

#pragma unroll
        for (int n = 0; n < 4; n++) {
            const int jl = wn * 32 + n * 8 + gq;
            uint32_t bh0 = bHi[jl * PS + kp];
            uint32_t bh1 = bHi[jl * PS + kp + 4];
            uint32_t bl0 = bLo[jl * PS + kp];
            uint32_t bl1 = bLo[jl * PS + kp + 4];
            mma_bf16(cA[n], ahi, bh0, bh1);   // Ah*Bh  (chain A)
            mma_bf16(cB[n], ahi, bl0, bl1);   // Ah*Bl  (chain B)
            mma_bf16(cB[n], alo, bh0, bh1);   // Al*Bh  (chain B)
        }
    }

    // Epilogue: sum chains, store.
#pragma unroll
    for (int n = 0; n < 4; n++) {
        const int rg  = row0 + wm * 16 + gq;
        const int col = col0 + wn * 32 + n * 8 + 2 * tq;
        *(float2*)&out[(long)rg * 128 + col] =
            make_float2(cA[n][0] + cB[n][0], cA[n][1] + cB[n][1]);
        *(float2*)&out[(long)(rg + 8) * 128 + col] =
            make_float2(cA[n][2] + cB[n][2], cA[n][3] + cB[n][3]);
    }
}

// ---------------------------------------------------------------------------
extern "C" void kernel_launch(void* const* d_in, const int* in_sizes, int n_in,
                              void* d_out, int out_size)
{
    const int*   entities = (const int*)d_in[0];
    const int*   history  = (const int*)d_in[1];
    const int*   hist_len = (const int*)d_in[2];
    const float* emb      = (const float*)d_in[3];
    const float* W        = (const float*)d_in[4];
    const float* bias     = (const float*)d_in[5];
    float*       out      = (float*)d_out;

    gather_kernel<<<B_ / 8, 256>>>(entities, history, hist_len,
                                   (const float4*)emb, (const float4*)W);

    const size_t smem = (size_t)4 * 64 * PS * sizeof(uint32_t);   // 68 KB
    cudaFuncSetAttribute(linear_kernel,
                         cudaFuncAttributeMaxDynamicSharedMemorySize,
                         (int)smem);
    linear_kernel<<<(B_ / 64) * 2, 256, smem>>>(bias, out);
}

// round 12
// speedup vs baseline: 1.2616x; 1.1295x over previous
#include <cuda_runtime.h>
#include <cuda_fp16.h>
#include <cstdint>

#define B_  16384
#define L_  50
#define PS  68     // padded row stride (uint32 words) for smem planes

// his as fp16 (hi only): per row 64 fp16x2 words
__device__ uint32_t g_hf[B_ * 64];
// W split fp16 hi/lo planes [128][64 words]
__device__ uint32_t g_whi[128 * 64];
__device__ uint32_t g_wlo[128 * 64];

__device__ __forceinline__ uint32_t pack_h2(__half a, __half b) {
    __half2 h2 = __halves2half2(a, b);
    return *(uint32_t*)&h2;
}
__device__ __forceinline__ void split_f16(float x, __half& h, __half& l) {
    h = __float2half_rn(x);
    l = __float2half_rn(x - __half2float(h));
}
__device__ __forceinline__ void mma_f16(float c[4], const uint32_t a[4],
                                        uint32_t b0, uint32_t b1) {
    asm volatile(
        "mma.sync.aligned.m16n8k16.row.col.f32.f16.f16.f32 "
        "{%0,%1,%2,%3}, {%4,%5,%6,%7}, {%8,%9}, {%0,%1,%2,%3};"
        : "+f"(c[0]), "+f"(c[1]), "+f"(c[2]), "+f"(c[3])
        : "r"(a[0]), "r"(a[1]), "r"(a[2]), "r"(a[3]), "r"(b0), "r"(b1));
}

// ---------------------------------------------------------------------------
// Kernel 1: masked gather-sum -> fp16 plane (1 STG.64/lane, 512B/warp).
// CTA 0 pre-splits W into fp16 hi/lo (hidden under DRAM wait).
// ---------------------------------------------------------------------------
__global__ __launch_bounds__(256) void gather_kernel(
    const int*    __restrict__ entities,
    const int*    __restrict__ history,
    const int*    __restrict__ hist_len,
    const float4* __restrict__ embv,
    const float4* __restrict__ Wv)
{
    const int warp = threadIdx.x >> 5;
    const int lane = threadIdx.x & 31;
    const int b    = (blockIdx.x << 3) + warp;

    if (blockIdx.x == 0) {
        for (int t = threadIdx.x; t < 128 * 32; t += 256) {
            const int j  = t >> 5;
            const int kv = t & 31;
            float4 w = Wv[j * 32 + kv];
            __half h0,l0,h1,l1,h2,l2,h3,l3;
            split_f16(w.x, h0, l0); split_f16(w.y, h1, l1);
            split_f16(w.z, h2, l2); split_f16(w.w, h3, l3);
            ((uint2*)g_whi)[j * 32 + kv] = make_uint2(pack_h2(h0,h1), pack_h2(h2,h3));
            ((uint2*)g_wlo)[j * 32 + kv] = make_uint2(pack_h2(l0,l1), pack_h2(l2,l3));
        }
    }

    __shared__ int sh_idx[8][52];

    const int n = hist_len[b];
    for (int l = lane; l < n; l += 32)
        sh_idx[warp][l] = history[b * L_ + l];
    __syncwarp();

    float4 a0 = make_float4(0.f, 0.f, 0.f, 0.f);
    float4 a1 = a0, a2 = a0, a3 = a0;

    int l = 0;
    for (; l + 4 <= n; l += 4) {
        const long i0 = sh_idx[warp][l + 0];
        const long i1 = sh_idx[warp][l + 1];
        const long i2 = sh_idx[warp][l + 2];
        const long i3 = sh_idx[warp][l + 3];
        float4 v0 = __ldg(&embv[i0 * 32 + lane]);
        float4 v1 = __ldg(&embv[i1 * 32 + lane]);
        float4 v2 = __ldg(&embv[i2 * 32 + lane]);
        float4 v3 = __ldg(&embv[i3 * 32 + lane]);
        a0.x += v0.x; a0.y += v0.y; a0.z += v0.z; a0.w += v0.w;
        a1.x += v1.x; a1.y += v1.y; a1.z += v1.z; a1.w += v1.w;
        a2.x += v2.x; a2.y += v2.y; a2.z += v2.z; a2.w += v2.w;
        a3.x += v3.x; a3.y += v3.y; a3.z += v3.z; a3.w += v3.w;
    }
    for (; l < n; l++) {
        const long i0 = sh_idx[warp][l];
        float4 v0 = __ldg(&embv[i0 * 32 + lane]);
        a0.x += v0.x; a0.y += v0.y; a0.z += v0.z; a0.w += v0.w;
    }

    float4 acc;
    acc.x = (a0.x + a1.x) + (a2.x + a3.x);
    acc.y = (a0.y + a1.y) + (a2.y + a3.y);
    acc.z = (a0.z + a1.z) + (a2.z + a3.z);
    acc.w = (a0.w + a1.w) + (a2.w + a3.w);

    if (n == 0)
        acc = __ldg(&embv[(long)entities[b] * 32 + lane]);

    // lane covers k = 4*lane..4*lane+3 -> words 2*lane, 2*lane+1
    ((uint2*)g_hf)[(long)b * 32 + lane] =
        make_uint2(pack_h2(__float2half_rn(acc.x), __float2half_rn(acc.y)),
                   pack_h2(__float2half_rn(acc.z), __float2half_rn(acc.w)));
}

// ---------------------------------------------------------------------------
// Kernel 2: out = his @ W^T + bias, 2-pass fp16 split (Ah*Bh + Ah*Bl).
// CTA = 64 rows x 64 cols, grid 512, ~52KB smem -> up to 4 CTAs/SM.
// ---------------------------------------------------------------------------
__global__ __launch_bounds__(256, 4) void linear_kernel(
    const float* __restrict__ bias,
    float*       __restrict__ out)
{
    extern __shared__ uint32_t sm[];
    uint32_t* aH  = sm;                 // [64][PS]
    uint32_t* bHi = aH  + 64 * PS;
    uint32_t* bLo = bHi + 64 * PS;

    const int tid  = threadIdx.x;
    const int lane = tid & 31;
    const int warp = tid >> 5;
    const int gq   = lane >> 2;
    const int tq   = lane & 3;
    const int wm   = warp >> 1;
    const int wn   = warp & 1;
    const int tile = blockIdx.x >> 1;
    const int half = blockIdx.x & 1;
    const int row0 = tile * 64;
    const int col0 = half * 64;

    // ---- Stage: pure vector copies ----
    {
        const uint4* sA  = (const uint4*)g_hf  + (long)row0 * 16;
        const uint4* sBh = (const uint4*)g_whi + (long)col0 * 16;
        const uint4* sBl = (const uint4*)g_wlo + (long)col0 * 16;
        for (int t = tid; t < 64 * 16; t += 256) {
            const int r = t >> 4;
            const int q = t & 15;
            *(uint4*)&aH [r * PS + q * 4] = sA[t];
            *(uint4*)&bHi[r * PS + q * 4] = sBh[t];
            *(uint4*)&bLo[r * PS + q * 4] = sBl[t];
        }
    }
    __syncthreads();

    float cA[4][4], cB[4][4];
#pragma unroll
    for (int n = 0; n < 4; n++) {
        const int col = col0 + wn * 32 + n * 8 + 2 * tq;
        const float b0 = __ldg(&bias[col]);
        const float b1 = __ldg(&bias[col + 1]);
        cA[n][0] = b0;  cA[n][1] = b1;
        cA[n][2] = b0;  cA[n][3] = b1;
        cB[n][0] = 0.f; cB[n][1] = 0.f;
        cB[n][2] = 0.f; cB[n][3] = 0.f;
    }

    const int r = wm * 16 + gq;
#pragma unroll
    for (int kt = 0; kt < 8; kt++) {
        const int kp = kt * 8 + tq;
        uint32_t ah[4];
        ah[0] = aH[r * PS + kp];
        ah[1] = aH[(r + 8) * PS + kp];
        ah[2] = aH[r * PS + kp + 4];
        ah[3] = aH[(r + 8) * PS + kp + 4];

#pragma unroll
        for (int n = 0; n < 4; n++) {
            const int jl = wn * 32 + n * 8 + gq;
            uint32_t bh0 = bHi[jl * PS + kp];
            uint32_t bh1 = bHi[jl * PS + kp + 4];
            uint32_t bl0 = bLo[jl * PS + kp];
            uint32_t bl1 = bLo[jl * PS + kp + 4];
            mma_f16(cA[n], ah, bh0, bh1);   // Ah*Bh  (chain A)
            mma_f16(cB[n], ah, bl0, bl1);   // Ah*Bl  (chain B)
        }
    }

    // Epilogue: sum chains, store.
#pragma unroll
    for (int n = 0; n < 4; n++) {
        const int rg  = row0 + wm * 16 + gq;
        const int col = col0 + wn * 32 + n * 8 + 2 * tq;
        *(float2*)&out[(long)rg * 128 + col] =
            make_float2(cA[n][0] + cB[n][0], cA[n][1] + cB[n][1]);
        *(float2*)&out[(long)(rg + 8) * 128 + col] =
            make_float2(cA[n][2] + cB[n][2], cA[n][3] + cB[n][3]);
    }
}

// ---------------------------------------------------------------------------
extern "C" void kernel_launch(void* const* d_in, const int* in_sizes, int n_in,
                              void* d_out, int out_size)
{
    const int*   entities = (const int*)d_in[0];
    const int*   history  = (const int*)d_in[1];
    const int*   hist_len = (const int*)d_in[2];
    const float* emb      = (const float*)d_in[3];
    const float* W        = (const float*)d_in[4];
    const float* bias     = (const float*)d_in[5];
    float*       out      = (float*)d_out;

    gather_kernel<<<B_ / 8, 256>>>(entities, history, hist_len,
                                   (const float4*)emb, (const float4*)W);

    const size_t smem = (size_t)3 * 64 * PS * sizeof(uint32_t);   // ~52 KB
    cudaFuncSetAttribute(linear_kernel,
                         cudaFuncAttributeMaxDynamicSharedMemorySize,
                         (int)smem);
    linear_kernel<<<(B_ / 64) * 2, 256, smem>>>(bias, out);
}

// round 13
// speedup vs baseline: 1.2739x; 1.0098x over previous
#include <cuda_runtime.h>
#include <cuda_fp16.h>
#include <cstdint>

#define B_  16384
#define L_  50
#define PS  68     // padded row stride (uint32 words) for smem planes

// his as fp16: per row 64 fp16x2 words
__device__ uint32_t g_hf[B_ * 64];
// W as fp16 [128][64 words]
__device__ uint32_t g_wf[128 * 64];

__device__ __forceinline__ uint32_t pack_h2(__half a, __half b) {
    __half2 h2 = __halves2half2(a, b);
    return *(uint32_t*)&h2;
}
__device__ __forceinline__ void mma_f16(float c[4], const uint32_t a[4],
                                        uint32_t b0, uint32_t b1) {
    asm volatile(
        "mma.sync.aligned.m16n8k16.row.col.f32.f16.f16.f32 "
        "{%0,%1,%2,%3}, {%4,%5,%6,%7}, {%8,%9}, {%0,%1,%2,%3};"
        : "+f"(c[0]), "+f"(c[1]), "+f"(c[2]), "+f"(c[3])
        : "r"(a[0]), "r"(a[1]), "r"(a[2]), "r"(a[3]), "r"(b0), "r"(b1));
}

// ---------------------------------------------------------------------------
// Kernel 1: masked gather-sum -> fp16 plane. CTA 0 converts W to fp16.
// ---------------------------------------------------------------------------
__global__ __launch_bounds__(256) void gather_kernel(
    const int*    __restrict__ entities,
    const int*    __restrict__ history,
    const int*    __restrict__ hist_len,
    const float4* __restrict__ embv,
    const float4* __restrict__ Wv)
{
    const int warp = threadIdx.x >> 5;
    const int lane = threadIdx.x & 31;
    const int b    = (blockIdx.x << 3) + warp;

    if (blockIdx.x == 0) {
        for (int t = threadIdx.x; t < 128 * 32; t += 256) {
            const int j  = t >> 5;
            const int kv = t & 31;
            float4 w = Wv[j * 32 + kv];
            ((uint2*)g_wf)[j * 32 + kv] = make_uint2(
                pack_h2(__float2half_rn(w.x), __float2half_rn(w.y)),
                pack_h2(__float2half_rn(w.z), __float2half_rn(w.w)));
        }
    }

    __shared__ int sh_idx[8][52];

    const int n = hist_len[b];
    for (int l = lane; l < n; l += 32)
        sh_idx[warp][l] = history[b * L_ + l];
    __syncwarp();

    float4 a0 = make_float4(0.f, 0.f, 0.f, 0.f);
    float4 a1 = a0, a2 = a0, a3 = a0;

    int l = 0;
    for (; l + 4 <= n; l += 4) {
        const long i0 = sh_idx[warp][l + 0];
        const long i1 = sh_idx[warp][l + 1];
        const long i2 = sh_idx[warp][l + 2];
        const long i3 = sh_idx[warp][l + 3];
        float4 v0 = __ldg(&embv[i0 * 32 + lane]);
        float4 v1 = __ldg(&embv[i1 * 32 + lane]);
        float4 v2 = __ldg(&embv[i2 * 32 + lane]);
        float4 v3 = __ldg(&embv[i3 * 32 + lane]);
        a0.x += v0.x; a0.y += v0.y; a0.z += v0.z; a0.w += v0.w;
        a1.x += v1.x; a1.y += v1.y; a1.z += v1.z; a1.w += v1.w;
        a2.x += v2.x; a2.y += v2.y; a2.z += v2.z; a2.w += v2.w;
        a3.x += v3.x; a3.y += v3.y; a3.z += v3.z; a3.w += v3.w;
    }
    for (; l < n; l++) {
        const long i0 = sh_idx[warp][l];
        float4 v0 = __ldg(&embv[i0 * 32 + lane]);
        a0.x += v0.x; a0.y += v0.y; a0.z += v0.z; a0.w += v0.w;
    }

    float4 acc;
    acc.x = (a0.x + a1.x) + (a2.x + a3.x);
    acc.y = (a0.y + a1.y) + (a2.y + a3.y);
    acc.z = (a0.z + a1.z) + (a2.z + a3.z);
    acc.w = (a0.w + a1.w) + (a2.w + a3.w);

    if (n == 0)
        acc = __ldg(&embv[(long)entities[b] * 32 + lane]);

    ((uint2*)g_hf)[(long)b * 32 + lane] =
        make_uint2(pack_h2(__float2half_rn(acc.x), __float2half_rn(acc.y)),
                   pack_h2(__float2half_rn(acc.z), __float2half_rn(acc.w)));
}

// ---------------------------------------------------------------------------
// Kernel 2: out = his @ W^T + bias, single-pass fp16 mma.m16n8k16.
// CTA = 64 rows x 64 cols, grid 512, ~35KB smem -> 6 CTAs/SM.
// ---------------------------------------------------------------------------
__global__ __launch_bounds__(256, 6) void linear_kernel(
    const float* __restrict__ bias,
    float*       __restrict__ out)
{
    extern __shared__ uint32_t sm[];
    uint32_t* aH = sm;                 // [64][PS]
    uint32_t* bH = aH + 64 * PS;       // [64][PS]

    const int tid  = threadIdx.x;
    const int lane = tid & 31;
    const int warp = tid >> 5;
    const int gq   = lane >> 2;
    const int tq   = lane & 3;
    const int wm   = warp >> 1;
    const int wn   = warp & 1;
    const int tile = blockIdx.x >> 1;
    const int half = blockIdx.x & 1;
    const int row0 = tile * 64;
    const int col0 = half * 64;

    // ---- Stage: pure vector copies ----
    {
        const uint4* sA = (const uint4*)g_hf + (long)row0 * 16;
        const uint4* sB = (const uint4*)g_wf + (long)col0 * 16;
        for (int t = tid; t < 64 * 16; t += 256) {
            const int r = t >> 4;
            const int q = t & 15;
            *(uint4*)&aH[r * PS + q * 4] = sA[t];
            *(uint4*)&bH[r * PS + q * 4] = sB[t];
        }
    }
    __syncthreads();

    float c[4][4];
#pragma unroll
    for (int n = 0; n < 4; n++) {
        const int col = col0 + wn * 32 + n * 8 + 2 * tq;
        const float b0 = __ldg(&bias[col]);
        const float b1 = __ldg(&bias[col + 1]);
        c[n][0] = b0; c[n][1] = b1;
        c[n][2] = b0; c[n][3] = b1;
    }

    const int r = wm * 16 + gq;
#pragma unroll
    for (int kt = 0; kt < 8; kt++) {
        const int kp = kt * 8 + tq;
        uint32_t ah[4];
        ah[0] = aH[r * PS + kp];
        ah[1] = aH[(r + 8) * PS + kp];
        ah[2] = aH[r * PS + kp + 4];
        ah[3] = aH[(r + 8) * PS + kp + 4];

#pragma unroll
        for (int n = 0; n < 4; n++) {
            const int jl = wn * 32 + n * 8 + gq;
            uint32_t b0 = bH[jl * PS + kp];
            uint32_t b1 = bH[jl * PS + kp + 4];
            mma_f16(c[n], ah, b0, b1);
        }
    }

    // Epilogue
#pragma unroll
    for (int n = 0; n < 4; n++) {
        const int rg  = row0 + wm * 16 + gq;
        const int col = col0 + wn * 32 + n * 8 + 2 * tq;
        *(float2*)&out[(long)rg * 128 + col]       = make_float2(c[n][0], c[n][1]);
        *(float2*)&out[(long)(rg + 8) * 128 + col] = make_float2(c[n][2], c[n][3]);
    }
}

// ---------------------------------------------------------------------------
extern "C" void kernel_launch(void* const* d_in, const int* in_sizes, int n_in,
                              void* d_out, int out_size)
{
    const int*   entities = (const int*)d_in[0];
    const int*   history  = (const int*)d_in[1];
    const int*   hist_len = (const int*)d_in[2];
    const float* emb      = (const float*)d_in[3];
    const float* W        = (const float*)d_in[4];
    const float* bias     = (const float*)d_in[5];
    float*       out      = (float*)d_out;

    gather_kernel<<<B_ / 8, 256>>>(entities, history, hist_len,
                                   (const float4*)emb, (const float4*)W);

    const size_t smem = (size_t)2 * 64 * PS * sizeof(uint32_t);   // ~35 KB
    cudaFuncSetAttribute(linear_kernel,
                         cudaFuncAttributeMaxDynamicSharedMemorySize,
                         (int)smem);
    linear_kernel<<<(B_ / 64) * 2, 256, smem>>>(bias, out);
}